// round 9
// baseline (speedup 1.0000x reference)
#include <cuda_runtime.h>
#include <math.h>

// ---------------------------------------------------------------------------
// AttentionalLaneLSTM: M=4096, N=256, EMB=64, H=128, ENC=128, T=100.
// ---------------------------------------------------------------------------
#define M_MAX   4096
#define T_STEPS 100
#define EMBD    64
#define HID     128
#define NOBS    256
#define ROWS    8       // rows per recurrent CTA
#define NP      4       // row pairs per recurrent CTA
#define XROWS   16      // rows per xgate CTA
#define XNP     8       // row pairs per xgate CTA

typedef unsigned long long ull;

// Scratch (device globals — no dynamic allocation allowed)
__device__ float g_scores[NOBS * T_STEPS];
// duplicated weights: WA[k][u] = (wi,wi,wf,wf), WB[k][u] = (wg,wg,wo,wo)
__device__ ulonglong2 g_WhA[2 * HID * HID];
__device__ ulonglong2 g_WhB[2 * HID * HID];
__device__ ulonglong2 g_WiA[2 * EMBD * HID];
__device__ ulonglong2 g_WiB[2 * EMBD * HID];
// x-gates per (dir,t,row-pair,u): XA=((i_e,i_o),(f_e,f_o)), XB=((g_e,g_o),(o_e,o_o))
__device__ ulonglong2 g_XA[2L * T_STEPS * (M_MAX / 2) * HID];
__device__ ulonglong2 g_XB[2L * T_STEPS * (M_MAX / 2) * HID];
__device__ float g_pre[M_MAX * 1024];

// ---------------------------------------------------------------------------
// f32x2 helpers (FFMA2 via PTX fma.rn.f32x2 on sm_103a)
// ---------------------------------------------------------------------------
__device__ __forceinline__ ull pack2(float a, float b) {
    ull r;
    asm("mov.b64 %0, {%1,%2};" : "=l"(r) : "f"(a), "f"(b));
    return r;
}
__device__ __forceinline__ float2 unpack2(ull v) {
    float2 r;
    asm("mov.b64 {%0,%1}, %2;" : "=f"(r.x), "=f"(r.y) : "l"(v));
    return r;
}
__device__ __forceinline__ void fma2(ull& acc, ull a, ull b) {
    asm("fma.rn.f32x2 %0, %1, %2, %0;" : "+l"(acc) : "l"(a), "l"(b));
}

__device__ __forceinline__ float sigf(float x) {
    return __fdividef(1.0f, 1.0f + __expf(-x));
}
__device__ __forceinline__ float tanhfast(float x) {
    return __fdividef(2.0f, 1.0f + __expf(-2.0f * x)) - 1.0f;
}

// ---------------------------------------------------------------------------
// Kernel 1: repack weights into duplicated-pair form. For (dir,k,u):
//   w_g = W[k][g*128+u];  WA = (w_i,w_i,w_f,w_f), WB = (w_g,w_g,w_o,w_o)
// One LDG.128 then yields ready-to-use f32x2 operands with ZERO MOVs.
// ---------------------------------------------------------------------------
__global__ void pack_kernel(const float* __restrict__ Wih_f,
                            const float* __restrict__ Whh_f,
                            const float* __restrict__ Wih_b,
                            const float* __restrict__ Whh_b) {
    int idx = blockIdx.x * blockDim.x + threadIdx.x;
    if (idx >= 2 * 192 * HID) return;
    int d   = idx / (192 * HID);
    int rem = idx % (192 * HID);
    int k   = rem / HID;
    int u   = rem % HID;
    if (k < HID) {
        const float* W = (d ? Whh_b : Whh_f) + k * 512;
        ulonglong2 A, B;
        A.x = pack2(W[u], W[u]);             A.y = pack2(W[128 + u], W[128 + u]);
        B.x = pack2(W[256 + u], W[256 + u]); B.y = pack2(W[384 + u], W[384 + u]);
        g_WhA[(d * HID + k) * HID + u] = A;
        g_WhB[(d * HID + k) * HID + u] = B;
    } else {
        int kk = k - HID;
        const float* W = (d ? Wih_b : Wih_f) + kk * 512;
        ulonglong2 A, B;
        A.x = pack2(W[u], W[u]);             A.y = pack2(W[128 + u], W[128 + u]);
        B.x = pack2(W[256 + u], W[256 + u]); B.y = pack2(W[384 + u], W[384 + u]);
        g_WiA[(d * EMBD + kk) * HID + u] = A;
        g_WiB[(d * EMBD + kk) * HID + u] = B;
    }
}

// ---------------------------------------------------------------------------
// Kernel 2: attention scores = softmax(relu(obs @ attn_W + attn_b), axis=1)
// ---------------------------------------------------------------------------
__global__ void attn_kernel(const float* __restrict__ obs,
                            const float* __restrict__ W,
                            const float* __restrict__ b) {
    int n = blockIdx.x;
    int tid = threadIdx.x;
    __shared__ float obs_s[128];
    __shared__ float red[128];

    obs_s[tid] = obs[n * 128 + tid];
    __syncthreads();

    float a = -1e30f;
    if (tid < T_STEPS) {
        a = b[tid];
#pragma unroll 8
        for (int k = 0; k < 128; k++) a = fmaf(obs_s[k], W[k * T_STEPS + tid], a);
        a = fmaxf(a, 0.0f);
    }
    red[tid] = a;
    __syncthreads();
    for (int s = 64; s > 0; s >>= 1) {
        if (tid < s) red[tid] = fmaxf(red[tid], red[tid + s]);
        __syncthreads();
    }
    float m = red[0];
    __syncthreads();
    float e = 0.0f;
    if (tid < T_STEPS) e = expf(a - m);
    red[tid] = e;
    __syncthreads();
    for (int s = 64; s > 0; s >>= 1) {
        if (tid < s) red[tid] += red[tid + s];
        __syncthreads();
    }
    float ssum = red[0];
    if (tid < T_STEPS) g_scores[n * T_STEPS + tid] = e / ssum;
}

// ---------------------------------------------------------------------------
// Kernel 3: x-gates for ALL (dir,t,m): xg = relu(feat4@embW+embB) @ Wih + b.
// Row-pair f32x2, duplicated weights (no MOVs). Per k: 2 LDG.128 + 4
// broadcast LDS.128 + 32 FFMA2. One barrier per t (double-buffered xs).
// ---------------------------------------------------------------------------
__global__ void __launch_bounds__(128, 5)
xgate_kernel(const float* __restrict__ lf,
             const float* __restrict__ embW, const float* __restrict__ embB,
             const float* __restrict__ b_f,  const float* __restrict__ b_b,
             int Mrows) {
    int nblk = Mrows / XROWS;
    int dir  = blockIdx.x / nblk;
    int mblk = blockIdx.x % nblk;
    int r0   = mblk * XROWS;
    int u    = threadIdx.x;

    __shared__ __align__(16) float2 xs[2][EMBD][XNP];  // 8 KB
    __shared__ float eW[4 * EMBD];
    __shared__ float eB[EMBD];

    eW[u]       = embW[u];
    eW[u + 128] = embW[u + 128];
    if (u < EMBD) eB[u] = embB[u];

    const float* bias = dir ? b_b : b_f;
    ull bI = pack2(bias[u],       bias[u]);
    ull bF = pack2(bias[128 + u], bias[128 + u]);
    ull bG = pack2(bias[256 + u], bias[256 + u]);
    ull bO = pack2(bias[384 + u], bias[384 + u]);
    const ulonglong2* WA = g_WiA + dir * EMBD * HID + u;
    const ulonglong2* WB = g_WiB + dir * EMBD * HID + u;
    __syncthreads();

    for (int t = 0; t < T_STEPS; t++) {
        int tb = t & 1;
        // stage x_t as row pairs: xs[e][pair] = (x_even, x_odd)
#pragma unroll
        for (int i = 0; i < 8; i++) {
            int idx = u + i * 128;            // 0..1023 over (r,e)
            int r = idx >> 6, e = idx & 63;
            const float4 f = *(const float4*)(lf + (r0 + r) * 600 + 200 + t * 4);
            float v = eB[e];
            v = fmaf(f.x, eW[e],        v);
            v = fmaf(f.y, eW[64  + e],  v);
            v = fmaf(f.z, eW[128 + e],  v);
            v = fmaf(f.w, eW[192 + e],  v);
            ((float*)&xs[tb][e][r >> 1])[r & 1] = fmaxf(v, 0.0f);
        }
        __syncthreads();

        ull aI[XNP], aF[XNP], aG[XNP], aO[XNP];
#pragma unroll
        for (int p = 0; p < XNP; p++) { aI[p] = bI; aF[p] = bF; aG[p] = bG; aO[p] = bO; }

#pragma unroll 4
        for (int k = 0; k < EMBD; k++) {
            ulonglong2 wA = WA[k * HID];
            ulonglong2 wB = WB[k * HID];
            ulonglong2 x01 = *(const ulonglong2*)&xs[tb][k][0];
            ulonglong2 x23 = *(const ulonglong2*)&xs[tb][k][2];
            ulonglong2 x45 = *(const ulonglong2*)&xs[tb][k][4];
            ulonglong2 x67 = *(const ulonglong2*)&xs[tb][k][6];
            fma2(aI[0],x01.x,wA.x); fma2(aF[0],x01.x,wA.y); fma2(aG[0],x01.x,wB.x); fma2(aO[0],x01.x,wB.y);
            fma2(aI[1],x01.y,wA.x); fma2(aF[1],x01.y,wA.y); fma2(aG[1],x01.y,wB.x); fma2(aO[1],x01.y,wB.y);
            fma2(aI[2],x23.x,wA.x); fma2(aF[2],x23.x,wA.y); fma2(aG[2],x23.x,wB.x); fma2(aO[2],x23.x,wB.y);
            fma2(aI[3],x23.y,wA.x); fma2(aF[3],x23.y,wA.y); fma2(aG[3],x23.y,wB.x); fma2(aO[3],x23.y,wB.y);
            fma2(aI[4],x45.x,wA.x); fma2(aF[4],x45.x,wA.y); fma2(aG[4],x45.x,wB.x); fma2(aO[4],x45.x,wB.y);
            fma2(aI[5],x45.y,wA.x); fma2(aF[5],x45.y,wA.y); fma2(aG[5],x45.y,wB.x); fma2(aO[5],x45.y,wB.y);
            fma2(aI[6],x67.x,wA.x); fma2(aF[6],x67.x,wA.y); fma2(aG[6],x67.x,wB.x); fma2(aO[6],x67.x,wB.y);
            fma2(aI[7],x67.y,wA.x); fma2(aF[7],x67.y,wA.y); fma2(aG[7],x67.y,wB.x); fma2(aO[7],x67.y,wB.y);
        }

        long base = ((long)(dir * T_STEPS + t) * (Mrows >> 1) + (r0 >> 1)) * HID + u;
#pragma unroll
        for (int p = 0; p < XNP; p++) {
            ulonglong2 oA; oA.x = aI[p]; oA.y = aF[p];
            ulonglong2 oB; oB.x = aG[p]; oB.y = aO[p];
            g_XA[base + (long)p * HID] = oA;
            g_XB[base + (long)p * HID] = oB;
        }
    }
}

// ---------------------------------------------------------------------------
// Kernel 4: recurrent bidirectional LSTM (h @ Whh; x-gates preloaded).
// Per k: 2 LDG.128 (dup weights) + 2 broadcast LDS.128 + 16 FFMA2, no MOVs.
// Double-buffered h -> one barrier/step; next-step xg loads hoisted over it.
// ---------------------------------------------------------------------------
__global__ void __launch_bounds__(128, 6)
lstm_kernel(const float* __restrict__ h0, const float* __restrict__ c0,
            const int*   __restrict__ mask, int Mrows) {
    int nblk = Mrows / ROWS;
    int dir  = blockIdx.x / nblk;
    int mblk = blockIdx.x % nblk;
    int r0   = mblk * ROWS;
    int u    = threadIdx.x;

    __shared__ __align__(16) float2 hs[2][HID][NP];  // 8 KB
    __shared__ int mrow[ROWS];
    if (u < ROWS) mrow[u] = mask[r0 + u];

    const ulonglong2* WA = g_WhA + dir * HID * HID + u;
    const ulonglong2* WB = g_WhB + dir * HID * HID + u;
    float h0v = h0[dir * HID + u];
    float c0v = c0[dir * HID + u];

    float cst[ROWS], hmax[ROWS], hatt[ROWS];
#pragma unroll
    for (int r = 0; r < ROWS; r++) { cst[r] = c0v; hmax[r] = -1e30f; hatt[r] = 0.0f; }
#pragma unroll
    for (int p = 0; p < NP; p++) hs[0][u][p] = make_float2(h0v, h0v);

    // prologue: x-gate accumulators for step 0 (bias folded in)
    ull aI[NP], aF[NP], aG[NP], aO[NP];
    {
        int t0 = dir ? (T_STEPS - 1) : 0;
        long base = ((long)(dir * T_STEPS + t0) * (Mrows >> 1) + (r0 >> 1)) * HID + u;
#pragma unroll
        for (int p = 0; p < NP; p++) {
            ulonglong2 xA = g_XA[base + (long)p * HID];
            ulonglong2 xB = g_XB[base + (long)p * HID];
            aI[p] = xA.x; aF[p] = xA.y; aG[p] = xB.x; aO[p] = xB.y;
        }
    }
    __syncthreads();

    int buf = 0;
    for (int s = 0; s < T_STEPS; s++) {
        int t = dir ? (T_STEPS - 1 - s) : s;

#pragma unroll 4
        for (int k = 0; k < HID; k++) {
            ulonglong2 wA  = WA[k * HID];
            ulonglong2 wB  = WB[k * HID];
            ulonglong2 h01 = *(const ulonglong2*)&hs[buf][k][0];
            ulonglong2 h23 = *(const ulonglong2*)&hs[buf][k][2];
            fma2(aI[0],h01.x,wA.x); fma2(aF[0],h01.x,wA.y); fma2(aG[0],h01.x,wB.x); fma2(aO[0],h01.x,wB.y);
            fma2(aI[1],h01.y,wA.x); fma2(aF[1],h01.y,wA.y); fma2(aG[1],h01.y,wB.x); fma2(aO[1],h01.y,wB.y);
            fma2(aI[2],h23.x,wA.x); fma2(aF[2],h23.x,wA.y); fma2(aG[2],h23.x,wB.x); fma2(aO[2],h23.x,wB.y);
            fma2(aI[3],h23.y,wA.x); fma2(aF[3],h23.y,wA.y); fma2(aG[3],h23.y,wB.x); fma2(aO[3],h23.y,wB.y);
        }

        // gate math + online reductions; publish h pairs to the other buffer
#pragma unroll
        for (int p = 0; p < NP; p++) {
            float2 iv = unpack2(aI[p]);
            float2 fv = unpack2(aF[p]);
            float2 gv = unpack2(aG[p]);
            float2 ov = unpack2(aO[p]);
            float ce = sigf(fv.x) * cst[2*p]     + sigf(iv.x) * tanhfast(gv.x);
            float co = sigf(fv.y) * cst[2*p + 1] + sigf(iv.y) * tanhfast(gv.y);
            cst[2*p] = ce; cst[2*p + 1] = co;
            float he = sigf(ov.x) * tanhfast(ce);
            float ho = sigf(ov.y) * tanhfast(co);
            hmax[2*p]     = fmaxf(hmax[2*p], he);
            hmax[2*p + 1] = fmaxf(hmax[2*p + 1], ho);
            float ae = __ldg(&g_scores[mrow[2*p]     * T_STEPS + t]);
            float ao = __ldg(&g_scores[mrow[2*p + 1] * T_STEPS + t]);
            hatt[2*p]     = fmaf(he, ae, hatt[2*p]);
            hatt[2*p + 1] = fmaf(ho, ao, hatt[2*p + 1]);
            hs[buf ^ 1][u][p] = make_float2(he, ho);
            if (t == 0) {
                g_pre[(r0 + 2*p)     * 1024 + dir * HID + u] = he;
                g_pre[(r0 + 2*p + 1) * 1024 + dir * HID + u] = ho;
            }
            if (t == T_STEPS - 1) {
                g_pre[(r0 + 2*p)     * 1024 + 256 + dir * HID + u] = he;
                g_pre[(r0 + 2*p + 1) * 1024 + 256 + dir * HID + u] = ho;
            }
        }

        // hoist next step's x-gate loads above the barrier (latency hiding)
        if (s + 1 < T_STEPS) {
            int tn = dir ? (T_STEPS - 2 - s) : (s + 1);
            long base = ((long)(dir * T_STEPS + tn) * (Mrows >> 1) + (r0 >> 1)) * HID + u;
#pragma unroll
            for (int p = 0; p < NP; p++) {
                ulonglong2 xA = g_XA[base + (long)p * HID];
                ulonglong2 xB = g_XB[base + (long)p * HID];
                aI[p] = xA.x; aF[p] = xA.y; aG[p] = xB.x; aO[p] = xB.y;
            }
        }
        __syncthreads();
        buf ^= 1;
    }

#pragma unroll
    for (int r = 0; r < ROWS; r++) {
        g_pre[(r0 + r) * 1024 + 512 + dir * HID + u] = hmax[r];
        g_pre[(r0 + r) * 1024 + 768 + dir * HID + u] = hatt[r];
    }
}

// ---------------------------------------------------------------------------
// Kernel 5: out = relu(pre(M,1024) @ enc_W(1024,128) + enc_b)
// ---------------------------------------------------------------------------
__global__ void __launch_bounds__(128)
out_kernel(const float* __restrict__ encW, const float* __restrict__ encB,
           float* __restrict__ out) {
    int r0 = blockIdx.x * ROWS;
    int c  = threadIdx.x;
    __shared__ float2 ps[ROWS / 2][64];

    float bc = encB[c];
    ull acc[ROWS / 2];
#pragma unroll
    for (int p = 0; p < ROWS / 2; p++) acc[p] = pack2(bc, bc);

    for (int kt = 0; kt < 1024; kt += 64) {
        __syncthreads();
#pragma unroll
        for (int i = 0; i < 4; i++) {
            int idx = c + i * 128;           // 0..511 over (r, kk)
            int r = idx >> 6, kk = idx & 63;
            ((float*)&ps[r >> 1][kk])[r & 1] = g_pre[(r0 + r) * 1024 + kt + kk];
        }
        __syncthreads();
#pragma unroll 4
        for (int kk = 0; kk < 64; kk++) {
            float w = encW[(kt + kk) * 128 + c];
            ull w2 = pack2(w, w);
#pragma unroll
            for (int p = 0; p < ROWS / 2; p++) {
                ull pv = *(const ull*)&ps[p][kk];
                fma2(acc[p], pv, w2);
            }
        }
    }
#pragma unroll
    for (int p = 0; p < ROWS / 2; p++) {
        float2 v = unpack2(acc[p]);
        out[(r0 + 2 * p)     * 128 + c] = fmaxf(v.x, 0.0f);
        out[(r0 + 2 * p + 1) * 128 + c] = fmaxf(v.y, 0.0f);
    }
}

// ---------------------------------------------------------------------------
// Launch
// ---------------------------------------------------------------------------
extern "C" void kernel_launch(void* const* d_in, const int* in_sizes, int n_in,
                              void* d_out, int out_size) {
    const float* lf    = (const float*)d_in[0];
    const float* obs   = (const float*)d_in[1];
    const float* embW  = (const float*)d_in[2];
    const float* embB  = (const float*)d_in[3];
    const float* attW  = (const float*)d_in[4];
    const float* attB  = (const float*)d_in[5];
    const float* Wih_f = (const float*)d_in[6];
    const float* Whh_f = (const float*)d_in[7];
    const float* b_f   = (const float*)d_in[8];
    const float* Wih_b = (const float*)d_in[9];
    const float* Whh_b = (const float*)d_in[10];
    const float* b_b   = (const float*)d_in[11];
    const float* h0    = (const float*)d_in[12];
    const float* c0    = (const float*)d_in[13];
    const float* encW  = (const float*)d_in[14];
    const float* encB  = (const float*)d_in[15];
    const int*   mask  = (const int*)d_in[16];

    int M    = in_sizes[16];       // 4096
    int Nobs = in_sizes[1] / 128;  // 256

    pack_kernel<<<(2 * 192 * HID + 255) / 256, 256>>>(Wih_f, Whh_f, Wih_b, Whh_b);
    attn_kernel<<<Nobs, 128>>>(obs, attW, attB);
    xgate_kernel<<<2 * (M / XROWS), 128>>>(lf, embW, embB, b_f, b_b, M);
    lstm_kernel<<<2 * (M / ROWS), 128>>>(h0, c0, mask, M);
    out_kernel<<<M / ROWS, 128>>>(encW, encB, (float*)d_out);
}

// round 10
// speedup vs baseline: 1.1335x; 1.1335x over previous
#include <cuda_runtime.h>
#include <math.h>

// ---------------------------------------------------------------------------
// AttentionalLaneLSTM: M=4096, N=256, EMB=64, H=128, ENC=128, T=100.
// ---------------------------------------------------------------------------
#define M_MAX   4096
#define T_STEPS 100
#define EMBD    64
#define HID     128
#define GDIM    512
#define NOBS    256
#define ROWS    16      // rows per recurrent/xgate CTA
#define NP      8       // row pairs per CTA

typedef unsigned long long ull;

// Scratch (device globals — no dynamic allocation allowed)
__device__ float g_scores[NOBS * T_STEPS];
__device__ __align__(16) float g_Whp[2 * HID  * GDIM];   // [dir][k][u*4+g], g=(i,f,g,o)
__device__ __align__(16) float g_Wip[2 * EMBD * GDIM];
// x-gates per (dir,t,row-pair,u): XA=((i_e,i_o),(f_e,f_o)), XB=((g_e,g_o),(o_e,o_o))
__device__ ulonglong2 g_XA[2L * T_STEPS * (M_MAX / 2) * HID];
__device__ ulonglong2 g_XB[2L * T_STEPS * (M_MAX / 2) * HID];
__device__ float g_pre[M_MAX * 1024];

// ---------------------------------------------------------------------------
// f32x2 helpers (FFMA2 via PTX fma.rn.f32x2 on sm_103a)
// ---------------------------------------------------------------------------
__device__ __forceinline__ ull pack2(float a, float b) {
    ull r;
    asm("mov.b64 %0, {%1,%2};" : "=l"(r) : "f"(a), "f"(b));
    return r;
}
__device__ __forceinline__ float2 unpack2(ull v) {
    float2 r;
    asm("mov.b64 {%0,%1}, %2;" : "=f"(r.x), "=f"(r.y) : "l"(v));
    return r;
}
__device__ __forceinline__ void fma2(ull& acc, ull a, ull b) {
    asm("fma.rn.f32x2 %0, %1, %2, %0;" : "+l"(acc) : "l"(a), "l"(b));
}

__device__ __forceinline__ float sigf(float x) {
    return __fdividef(1.0f, 1.0f + __expf(-x));
}
__device__ __forceinline__ float tanhfast(float x) {
    return __fdividef(2.0f, 1.0f + __expf(-2.0f * x)) - 1.0f;
}

// ---------------------------------------------------------------------------
// Kernel 1: repack weights into [dir][k][u*4 + gate] (gate-interleaved): one
// LDG.128 per (k,u) carries all 4 gate weights of unit u (16B natural layout).
// ---------------------------------------------------------------------------
__global__ void pack_kernel(const float* __restrict__ Wih_f,
                            const float* __restrict__ Whh_f,
                            const float* __restrict__ Wih_b,
                            const float* __restrict__ Whh_b) {
    int idx = blockIdx.x * blockDim.x + threadIdx.x;
    if (idx >= 2 * 192 * GDIM) return;
    int d   = idx / (192 * GDIM);
    int rem = idx % (192 * GDIM);
    int k   = rem / GDIM;
    int q   = rem % GDIM;
    int u   = q >> 2;
    int g   = q & 3;
    int col = g * HID + u;
    if (k < HID) {
        const float* Whh = d ? Whh_b : Whh_f;
        g_Whp[(d * HID + k) * GDIM + q] = Whh[k * GDIM + col];
    } else {
        const float* Wih = d ? Wih_b : Wih_f;
        g_Wip[(d * EMBD + (k - HID)) * GDIM + q] = Wih[(k - HID) * GDIM + col];
    }
}

// ---------------------------------------------------------------------------
// Kernel 2: attention scores = softmax(relu(obs @ attn_W + attn_b), axis=1)
// ---------------------------------------------------------------------------
__global__ void attn_kernel(const float* __restrict__ obs,
                            const float* __restrict__ W,
                            const float* __restrict__ b) {
    int n = blockIdx.x;
    int tid = threadIdx.x;
    __shared__ float obs_s[128];
    __shared__ float red[128];

    obs_s[tid] = obs[n * 128 + tid];
    __syncthreads();

    float a = -1e30f;
    if (tid < T_STEPS) {
        a = b[tid];
#pragma unroll 8
        for (int k = 0; k < 128; k++) a = fmaf(obs_s[k], W[k * T_STEPS + tid], a);
        a = fmaxf(a, 0.0f);
    }
    red[tid] = a;
    __syncthreads();
    for (int s = 64; s > 0; s >>= 1) {
        if (tid < s) red[tid] = fmaxf(red[tid], red[tid + s]);
        __syncthreads();
    }
    float m = red[0];
    __syncthreads();
    float e = 0.0f;
    if (tid < T_STEPS) e = expf(a - m);
    red[tid] = e;
    __syncthreads();
    for (int s = 64; s > 0; s >>= 1) {
        if (tid < s) red[tid] += red[tid + s];
        __syncthreads();
    }
    float ssum = red[0];
    if (tid < T_STEPS) g_scores[n * T_STEPS + tid] = e / ssum;
}

// ---------------------------------------------------------------------------
// Kernel 3: x-gates for ALL (dir,t,m): xg = relu(feat4@embW+embB) @ Wih + b.
// ROWS=16 row-pairs: per k = 1 LDG.128 + 8 MOV + 4 LDS.128 + 32 FFMA2 (71% fma).
// Double-buffered xs -> one barrier per t.
// ---------------------------------------------------------------------------
__global__ void __launch_bounds__(128, 3)
xgate_kernel(const float* __restrict__ lf,
             const float* __restrict__ embW, const float* __restrict__ embB,
             const float* __restrict__ b_f,  const float* __restrict__ b_b,
             int Mrows) {
    int nblk = Mrows / ROWS;
    int dir  = blockIdx.x / nblk;
    int mblk = blockIdx.x % nblk;
    int r0   = mblk * ROWS;
    int u    = threadIdx.x;

    __shared__ __align__(16) float2 xs[2][EMBD][NP];  // 8 KB
    __shared__ float eW[4 * EMBD];
    __shared__ float eB[EMBD];

    eW[u]       = embW[u];
    eW[u + 128] = embW[u + 128];
    if (u < EMBD) eB[u] = embB[u];

    const float* bias = dir ? b_b : b_f;
    float bg0 = bias[u], bg1 = bias[128 + u], bg2 = bias[256 + u], bg3 = bias[384 + u];
    ull bI = pack2(bg0, bg0), bF = pack2(bg1, bg1);
    ull bG = pack2(bg2, bg2), bO = pack2(bg3, bg3);
    const float4* Wp = (const float4*)(g_Wip + dir * EMBD * GDIM) + u;
    __syncthreads();

    for (int t = 0; t < T_STEPS; t++) {
        int tb = t & 1;
        // stage x_t as row pairs: xs[e][p] = (x_even, x_odd)
#pragma unroll
        for (int i = 0; i < 8; i++) {
            int idx = u + i * 128;            // 0..1023 over (r,e)
            int r = idx >> 6, e = idx & 63;
            const float4 f = *(const float4*)(lf + (r0 + r) * 600 + 200 + t * 4);
            float v = eB[e];
            v = fmaf(f.x, eW[e],        v);
            v = fmaf(f.y, eW[64  + e],  v);
            v = fmaf(f.z, eW[128 + e],  v);
            v = fmaf(f.w, eW[192 + e],  v);
            ((float*)&xs[tb][e][r >> 1])[r & 1] = fmaxf(v, 0.0f);
        }
        __syncthreads();

        ull aI[NP], aF[NP], aG[NP], aO[NP];
#pragma unroll
        for (int p = 0; p < NP; p++) { aI[p] = bI; aF[p] = bF; aG[p] = bG; aO[p] = bO; }

#pragma unroll 2
        for (int k = 0; k < EMBD; k++) {
            float4 w4 = Wp[k * 128];
            ull w0 = pack2(w4.x, w4.x);
            ull w1 = pack2(w4.y, w4.y);
            ull w2 = pack2(w4.z, w4.z);
            ull w3 = pack2(w4.w, w4.w);
#pragma unroll
            for (int q = 0; q < NP / 2; q++) {
                ulonglong2 x2 = *(const ulonglong2*)&xs[tb][k][2 * q];
                fma2(aI[2*q],   x2.x, w0); fma2(aF[2*q],   x2.x, w1);
                fma2(aG[2*q],   x2.x, w2); fma2(aO[2*q],   x2.x, w3);
                fma2(aI[2*q+1], x2.y, w0); fma2(aF[2*q+1], x2.y, w1);
                fma2(aG[2*q+1], x2.y, w2); fma2(aO[2*q+1], x2.y, w3);
            }
        }

        long base = ((long)(dir * T_STEPS + t) * (Mrows >> 1) + (r0 >> 1)) * HID + u;
#pragma unroll
        for (int p = 0; p < NP; p++) {
            ulonglong2 oA; oA.x = aI[p]; oA.y = aF[p];
            ulonglong2 oB; oB.x = aG[p]; oB.y = aO[p];
            g_XA[base + (long)p * HID] = oA;
            g_XB[base + (long)p * HID] = oB;
        }
    }
}

// ---------------------------------------------------------------------------
// Kernel 4: recurrent bidirectional LSTM (h @ Whh; x-gates preloaded).
// ROWS=16 row-pairs: per k = 1 LDG.128 + 8 MOV + 4 LDS.128 + 32 FFMA2.
// Double-buffered h -> one barrier/step; next-step xg loads hoisted over it.
// ---------------------------------------------------------------------------
__global__ void __launch_bounds__(128, 3)
lstm_kernel(const float* __restrict__ h0, const float* __restrict__ c0,
            const int*   __restrict__ mask, int Mrows) {
    int nblk = Mrows / ROWS;
    int dir  = blockIdx.x / nblk;
    int mblk = blockIdx.x % nblk;
    int r0   = mblk * ROWS;
    int u    = threadIdx.x;

    __shared__ __align__(16) float2 hs[2][HID][NP];  // 16 KB
    __shared__ int mrow[ROWS];
    if (u < ROWS) mrow[u] = mask[r0 + u];

    const float4* Wp = (const float4*)(g_Whp + dir * HID * GDIM) + u;
    float h0v = h0[dir * HID + u];
    float c0v = c0[dir * HID + u];

    float cst[ROWS], hmax[ROWS], hatt[ROWS];
#pragma unroll
    for (int r = 0; r < ROWS; r++) { cst[r] = c0v; hmax[r] = -1e30f; hatt[r] = 0.0f; }
#pragma unroll
    for (int p = 0; p < NP; p++) hs[0][u][p] = make_float2(h0v, h0v);

    // prologue: x-gate accumulators for step 0 (bias folded in)
    ull aI[NP], aF[NP], aG[NP], aO[NP];
    {
        int t0 = dir ? (T_STEPS - 1) : 0;
        long base = ((long)(dir * T_STEPS + t0) * (Mrows >> 1) + (r0 >> 1)) * HID + u;
#pragma unroll
        for (int p = 0; p < NP; p++) {
            ulonglong2 xA = g_XA[base + (long)p * HID];
            ulonglong2 xB = g_XB[base + (long)p * HID];
            aI[p] = xA.x; aF[p] = xA.y; aG[p] = xB.x; aO[p] = xB.y;
        }
    }
    __syncthreads();

    int buf = 0;
    for (int s = 0; s < T_STEPS; s++) {
        int t = dir ? (T_STEPS - 1 - s) : s;

#pragma unroll 2
        for (int k = 0; k < HID; k++) {
            float4 w4 = Wp[k * 128];
            ull w0 = pack2(w4.x, w4.x);
            ull w1 = pack2(w4.y, w4.y);
            ull w2 = pack2(w4.z, w4.z);
            ull w3 = pack2(w4.w, w4.w);
#pragma unroll
            for (int q = 0; q < NP / 2; q++) {
                ulonglong2 h2 = *(const ulonglong2*)&hs[buf][k][2 * q];
                fma2(aI[2*q],   h2.x, w0); fma2(aF[2*q],   h2.x, w1);
                fma2(aG[2*q],   h2.x, w2); fma2(aO[2*q],   h2.x, w3);
                fma2(aI[2*q+1], h2.y, w0); fma2(aF[2*q+1], h2.y, w1);
                fma2(aG[2*q+1], h2.y, w2); fma2(aO[2*q+1], h2.y, w3);
            }
        }

        // gate math + online reductions; publish h pairs to the other buffer
#pragma unroll
        for (int p = 0; p < NP; p++) {
            float2 iv = unpack2(aI[p]);
            float2 fv = unpack2(aF[p]);
            float2 gv = unpack2(aG[p]);
            float2 ov = unpack2(aO[p]);
            float ce = sigf(fv.x) * cst[2*p]     + sigf(iv.x) * tanhfast(gv.x);
            float co = sigf(fv.y) * cst[2*p + 1] + sigf(iv.y) * tanhfast(gv.y);
            cst[2*p] = ce; cst[2*p + 1] = co;
            float he = sigf(ov.x) * tanhfast(ce);
            float ho = sigf(ov.y) * tanhfast(co);
            hmax[2*p]     = fmaxf(hmax[2*p], he);
            hmax[2*p + 1] = fmaxf(hmax[2*p + 1], ho);
            float ae = __ldg(&g_scores[mrow[2*p]     * T_STEPS + t]);
            float ao = __ldg(&g_scores[mrow[2*p + 1] * T_STEPS + t]);
            hatt[2*p]     = fmaf(he, ae, hatt[2*p]);
            hatt[2*p + 1] = fmaf(ho, ao, hatt[2*p + 1]);
            hs[buf ^ 1][u][p] = make_float2(he, ho);
            if (t == 0) {
                g_pre[(r0 + 2*p)     * 1024 + dir * HID + u] = he;
                g_pre[(r0 + 2*p + 1) * 1024 + dir * HID + u] = ho;
            }
            if (t == T_STEPS - 1) {
                g_pre[(r0 + 2*p)     * 1024 + 256 + dir * HID + u] = he;
                g_pre[(r0 + 2*p + 1) * 1024 + 256 + dir * HID + u] = ho;
            }
        }

        // hoist next step's x-gate loads above the barrier (latency hiding)
        if (s + 1 < T_STEPS) {
            int tn = dir ? (T_STEPS - 2 - s) : (s + 1);
            long base = ((long)(dir * T_STEPS + tn) * (Mrows >> 1) + (r0 >> 1)) * HID + u;
#pragma unroll
            for (int p = 0; p < NP; p++) {
                ulonglong2 xA = g_XA[base + (long)p * HID];
                ulonglong2 xB = g_XB[base + (long)p * HID];
                aI[p] = xA.x; aF[p] = xA.y; aG[p] = xB.x; aO[p] = xB.y;
            }
        }
        __syncthreads();  // single barrier per step (double-buffered h)
        buf ^= 1;
    }

#pragma unroll
    for (int r = 0; r < ROWS; r++) {
        g_pre[(r0 + r) * 1024 + 512 + dir * HID + u] = hmax[r];
        g_pre[(r0 + r) * 1024 + 768 + dir * HID + u] = hatt[r];
    }
}

// ---------------------------------------------------------------------------
// Kernel 5: out = relu(pre(M,1024) @ enc_W(1024,128) + enc_b)
// ---------------------------------------------------------------------------
__global__ void __launch_bounds__(128)
out_kernel(const float* __restrict__ encW, const float* __restrict__ encB,
           float* __restrict__ out) {
    const int R2 = 8;
    int r0 = blockIdx.x * R2;
    int c  = threadIdx.x;
    __shared__ float2 ps[R2 / 2][64];

    float bc = encB[c];
    ull acc[R2 / 2];
#pragma unroll
    for (int p = 0; p < R2 / 2; p++) acc[p] = pack2(bc, bc);

    for (int kt = 0; kt < 1024; kt += 64) {
        __syncthreads();
#pragma unroll
        for (int i = 0; i < 4; i++) {
            int idx = c + i * 128;           // 0..511 over (r, kk)
            int r = idx >> 6, kk = idx & 63;
            ((float*)&ps[r >> 1][kk])[r & 1] = g_pre[(r0 + r) * 1024 + kt + kk];
        }
        __syncthreads();
#pragma unroll 4
        for (int kk = 0; kk < 64; kk++) {
            float w = encW[(kt + kk) * 128 + c];
            ull w2 = pack2(w, w);
#pragma unroll
            for (int p = 0; p < R2 / 2; p++) {
                ull pv = *(const ull*)&ps[p][kk];
                fma2(acc[p], pv, w2);
            }
        }
    }
#pragma unroll
    for (int p = 0; p < R2 / 2; p++) {
        float2 v = unpack2(acc[p]);
        out[(r0 + 2 * p)     * 128 + c] = fmaxf(v.x, 0.0f);
        out[(r0 + 2 * p + 1) * 128 + c] = fmaxf(v.y, 0.0f);
    }
}

// ---------------------------------------------------------------------------
// Launch
// ---------------------------------------------------------------------------
extern "C" void kernel_launch(void* const* d_in, const int* in_sizes, int n_in,
                              void* d_out, int out_size) {
    const float* lf    = (const float*)d_in[0];
    const float* obs   = (const float*)d_in[1];
    const float* embW  = (const float*)d_in[2];
    const float* embB  = (const float*)d_in[3];
    const float* attW  = (const float*)d_in[4];
    const float* attB  = (const float*)d_in[5];
    const float* Wih_f = (const float*)d_in[6];
    const float* Whh_f = (const float*)d_in[7];
    const float* b_f   = (const float*)d_in[8];
    const float* Wih_b = (const float*)d_in[9];
    const float* Whh_b = (const float*)d_in[10];
    const float* b_b   = (const float*)d_in[11];
    const float* h0    = (const float*)d_in[12];
    const float* c0    = (const float*)d_in[13];
    const float* encW  = (const float*)d_in[14];
    const float* encB  = (const float*)d_in[15];
    const int*   mask  = (const int*)d_in[16];

    int M    = in_sizes[16];       // 4096
    int Nobs = in_sizes[1] / 128;  // 256

    pack_kernel<<<(2 * 192 * GDIM + 255) / 256, 256>>>(Wih_f, Whh_f, Wih_b, Whh_b);
    attn_kernel<<<Nobs, 128>>>(obs, attW, attB);
    xgate_kernel<<<2 * (M / ROWS), 128>>>(lf, embW, embB, b_f, b_b, M);
    lstm_kernel<<<2 * (M / ROWS), 128>>>(h0, c0, mask, M);
    out_kernel<<<M / 8, 128>>>(encW, encB, (float*)d_out);
}

// round 12
// speedup vs baseline: 1.1339x; 1.0004x over previous
#include <cuda_runtime.h>
#include <math.h>

// ---------------------------------------------------------------------------
// AttentionalLaneLSTM: M=4096, N=256, EMB=64, H=128, ENC=128, T=100.
// ---------------------------------------------------------------------------
#define M_MAX   4096
#define T_STEPS 100
#define EMBD    64
#define HID     128
#define GDIM    512
#define NOBS    256
#define ROWS    16      // rows per recurrent/xgate CTA
#define NP      8       // row pairs per CTA

typedef unsigned long long ull;

// Scratch (device globals — no dynamic allocation allowed)
__device__ float g_scores[NOBS * T_STEPS];
__device__ __align__(16) float g_Whp[2 * HID  * GDIM];   // [dir][k][u*4+g], g=(i,f,g,o)
__device__ __align__(16) float g_Wip[2 * EMBD * GDIM];
// x-gates per (dir,t,row-pair,u): XA=((i_e,i_o),(f_e,f_o)), XB=((g_e,g_o),(o_e,o_o))
__device__ ulonglong2 g_XA[2L * T_STEPS * (M_MAX / 2) * HID];
__device__ ulonglong2 g_XB[2L * T_STEPS * (M_MAX / 2) * HID];
__device__ float g_pre[M_MAX * 1024];

// ---------------------------------------------------------------------------
// f32x2 helpers (FFMA2 via PTX fma.rn.f32x2 on sm_103a)
// ---------------------------------------------------------------------------
__device__ __forceinline__ ull pack2(float a, float b) {
    ull r;
    asm("mov.b64 %0, {%1,%2};" : "=l"(r) : "f"(a), "f"(b));
    return r;
}
__device__ __forceinline__ float2 unpack2(ull v) {
    float2 r;
    asm("mov.b64 {%0,%1}, %2;" : "=f"(r.x), "=f"(r.y) : "l"(v));
    return r;
}
__device__ __forceinline__ void fma2(ull& acc, ull a, ull b) {
    asm("fma.rn.f32x2 %0, %1, %2, %0;" : "+l"(acc) : "l"(a), "l"(b));
}

__device__ __forceinline__ float sigf(float x) {
    return __fdividef(1.0f, 1.0f + __expf(-x));
}
__device__ __forceinline__ float tanhfast(float x) {
    return __fdividef(2.0f, 1.0f + __expf(-2.0f * x)) - 1.0f;
}

// ---------------------------------------------------------------------------
// Kernel 1: repack weights into [dir][k][u*4 + gate] (gate-interleaved): one
// LDG.128 per (k,u) carries all 4 gate weights of unit u (16B natural layout).
// ---------------------------------------------------------------------------
__global__ void pack_kernel(const float* __restrict__ Wih_f,
                            const float* __restrict__ Whh_f,
                            const float* __restrict__ Wih_b,
                            const float* __restrict__ Whh_b) {
    int idx = blockIdx.x * blockDim.x + threadIdx.x;
    if (idx >= 2 * 192 * GDIM) return;
    int d   = idx / (192 * GDIM);
    int rem = idx % (192 * GDIM);
    int k   = rem / GDIM;
    int q   = rem % GDIM;
    int u   = q >> 2;
    int g   = q & 3;
    int col = g * HID + u;
    if (k < HID) {
        const float* Whh = d ? Whh_b : Whh_f;
        g_Whp[(d * HID + k) * GDIM + q] = Whh[k * GDIM + col];
    } else {
        const float* Wih = d ? Wih_b : Wih_f;
        g_Wip[(d * EMBD + (k - HID)) * GDIM + q] = Wih[(k - HID) * GDIM + col];
    }
}

// ---------------------------------------------------------------------------
// Kernel 2: attention scores = softmax(relu(obs @ attn_W + attn_b), axis=1)
// ---------------------------------------------------------------------------
__global__ void attn_kernel(const float* __restrict__ obs,
                            const float* __restrict__ W,
                            const float* __restrict__ b) {
    int n = blockIdx.x;
    int tid = threadIdx.x;
    __shared__ float obs_s[128];
    __shared__ float red[128];

    obs_s[tid] = obs[n * 128 + tid];
    __syncthreads();

    float a = -1e30f;
    if (tid < T_STEPS) {
        a = b[tid];
#pragma unroll 8
        for (int k = 0; k < 128; k++) a = fmaf(obs_s[k], W[k * T_STEPS + tid], a);
        a = fmaxf(a, 0.0f);
    }
    red[tid] = a;
    __syncthreads();
    for (int s = 64; s > 0; s >>= 1) {
        if (tid < s) red[tid] = fmaxf(red[tid], red[tid + s]);
        __syncthreads();
    }
    float m = red[0];
    __syncthreads();
    float e = 0.0f;
    if (tid < T_STEPS) e = expf(a - m);
    red[tid] = e;
    __syncthreads();
    for (int s = 64; s > 0; s >>= 1) {
        if (tid < s) red[tid] += red[tid + s];
        __syncthreads();
    }
    float ssum = red[0];
    if (tid < T_STEPS) g_scores[n * T_STEPS + tid] = e / ssum;
}

// ---------------------------------------------------------------------------
// Kernel 3: x-gates for ALL (dir,t,m): xg = relu(feat4@embW+embB) @ Wih + b.
// ROWS=16 row-pairs: per k = 1 LDG.128 + 8 MOV + 4 LDS.128 + 32 FFMA2 (71% fma).
// Double-buffered xs -> one barrier per t.
// ---------------------------------------------------------------------------
__global__ void __launch_bounds__(128, 3)
xgate_kernel(const float* __restrict__ lf,
             const float* __restrict__ embW, const float* __restrict__ embB,
             const float* __restrict__ b_f,  const float* __restrict__ b_b,
             int Mrows) {
    int nblk = Mrows / ROWS;
    int dir  = blockIdx.x / nblk;
    int mblk = blockIdx.x % nblk;
    int r0   = mblk * ROWS;
    int u    = threadIdx.x;

    __shared__ __align__(16) float2 xs[2][EMBD][NP];  // 8 KB
    __shared__ float eW[4 * EMBD];
    __shared__ float eB[EMBD];

    eW[u]       = embW[u];
    eW[u + 128] = embW[u + 128];
    if (u < EMBD) eB[u] = embB[u];

    const float* bias = dir ? b_b : b_f;
    float bg0 = bias[u], bg1 = bias[128 + u], bg2 = bias[256 + u], bg3 = bias[384 + u];
    ull bI = pack2(bg0, bg0), bF = pack2(bg1, bg1);
    ull bG = pack2(bg2, bg2), bO = pack2(bg3, bg3);
    const float4* Wp = (const float4*)(g_Wip + dir * EMBD * GDIM) + u;
    __syncthreads();

    for (int t = 0; t < T_STEPS; t++) {
        int tb = t & 1;
        // stage x_t as row pairs: xs[e][p] = (x_even, x_odd)
#pragma unroll
        for (int i = 0; i < 8; i++) {
            int idx = u + i * 128;            // 0..1023 over (r,e)
            int r = idx >> 6, e = idx & 63;
            const float4 f = *(const float4*)(lf + (r0 + r) * 600 + 200 + t * 4);
            float v = eB[e];
            v = fmaf(f.x, eW[e],        v);
            v = fmaf(f.y, eW[64  + e],  v);
            v = fmaf(f.z, eW[128 + e],  v);
            v = fmaf(f.w, eW[192 + e],  v);
            ((float*)&xs[tb][e][r >> 1])[r & 1] = fmaxf(v, 0.0f);
        }
        __syncthreads();

        ull aI[NP], aF[NP], aG[NP], aO[NP];
#pragma unroll
        for (int p = 0; p < NP; p++) { aI[p] = bI; aF[p] = bF; aG[p] = bG; aO[p] = bO; }

#pragma unroll 2
        for (int k = 0; k < EMBD; k++) {
            float4 w4 = Wp[k * 128];
            ull w0 = pack2(w4.x, w4.x);
            ull w1 = pack2(w4.y, w4.y);
            ull w2 = pack2(w4.z, w4.z);
            ull w3 = pack2(w4.w, w4.w);
#pragma unroll
            for (int q = 0; q < NP / 2; q++) {
                ulonglong2 x2 = *(const ulonglong2*)&xs[tb][k][2 * q];
                fma2(aI[2*q],   x2.x, w0); fma2(aF[2*q],   x2.x, w1);
                fma2(aG[2*q],   x2.x, w2); fma2(aO[2*q],   x2.x, w3);
                fma2(aI[2*q+1], x2.y, w0); fma2(aF[2*q+1], x2.y, w1);
                fma2(aG[2*q+1], x2.y, w2); fma2(aO[2*q+1], x2.y, w3);
            }
        }

        long base = ((long)(dir * T_STEPS + t) * (Mrows >> 1) + (r0 >> 1)) * HID + u;
#pragma unroll
        for (int p = 0; p < NP; p++) {
            ulonglong2 oA; oA.x = aI[p]; oA.y = aF[p];
            ulonglong2 oB; oB.x = aG[p]; oB.y = aO[p];
            g_XA[base + (long)p * HID] = oA;
            g_XB[base + (long)p * HID] = oB;
        }
    }
}

// ---------------------------------------------------------------------------
// Kernel 4: recurrent bidirectional LSTM (h @ Whh; x-gates preloaded).
// ROWS=16 row-pairs: per k = 1 LDG.128 + 8 MOV + 4 LDS.128 + 32 FFMA2.
// Double-buffered h -> one barrier/step; next-step xg loads hoisted over it.
// ---------------------------------------------------------------------------
__global__ void __launch_bounds__(128, 3)
lstm_kernel(const float* __restrict__ h0, const float* __restrict__ c0,
            const int*   __restrict__ mask, int Mrows) {
    int nblk = Mrows / ROWS;
    int dir  = blockIdx.x / nblk;
    int mblk = blockIdx.x % nblk;
    int r0   = mblk * ROWS;
    int u    = threadIdx.x;

    __shared__ __align__(16) float2 hs[2][HID][NP];  // 16 KB
    __shared__ int mrow[ROWS];
    if (u < ROWS) mrow[u] = mask[r0 + u];

    const float4* Wp = (const float4*)(g_Whp + dir * HID * GDIM) + u;
    float h0v = h0[dir * HID + u];
    float c0v = c0[dir * HID + u];

    float cst[ROWS], hmax[ROWS], hatt[ROWS];
#pragma unroll
    for (int r = 0; r < ROWS; r++) { cst[r] = c0v; hmax[r] = -1e30f; hatt[r] = 0.0f; }
#pragma unroll
    for (int p = 0; p < NP; p++) hs[0][u][p] = make_float2(h0v, h0v);

    // prologue: x-gate accumulators for step 0 (bias folded in)
    ull aI[NP], aF[NP], aG[NP], aO[NP];
    {
        int t0 = dir ? (T_STEPS - 1) : 0;
        long base = ((long)(dir * T_STEPS + t0) * (Mrows >> 1) + (r0 >> 1)) * HID + u;
#pragma unroll
        for (int p = 0; p < NP; p++) {
            ulonglong2 xA = g_XA[base + (long)p * HID];
            ulonglong2 xB = g_XB[base + (long)p * HID];
            aI[p] = xA.x; aF[p] = xA.y; aG[p] = xB.x; aO[p] = xB.y;
        }
    }
    __syncthreads();

    int buf = 0;
    for (int s = 0; s < T_STEPS; s++) {
        int t = dir ? (T_STEPS - 1 - s) : s;

#pragma unroll 2
        for (int k = 0; k < HID; k++) {
            float4 w4 = Wp[k * 128];
            ull w0 = pack2(w4.x, w4.x);
            ull w1 = pack2(w4.y, w4.y);
            ull w2 = pack2(w4.z, w4.z);
            ull w3 = pack2(w4.w, w4.w);
#pragma unroll
            for (int q = 0; q < NP / 2; q++) {
                ulonglong2 h2 = *(const ulonglong2*)&hs[buf][k][2 * q];
                fma2(aI[2*q],   h2.x, w0); fma2(aF[2*q],   h2.x, w1);
                fma2(aG[2*q],   h2.x, w2); fma2(aO[2*q],   h2.x, w3);
                fma2(aI[2*q+1], h2.y, w0); fma2(aF[2*q+1], h2.y, w1);
                fma2(aG[2*q+1], h2.y, w2); fma2(aO[2*q+1], h2.y, w3);
            }
        }

        // gate math + online reductions; publish h pairs to the other buffer
#pragma unroll
        for (int p = 0; p < NP; p++) {
            float2 iv = unpack2(aI[p]);
            float2 fv = unpack2(aF[p]);
            float2 gv = unpack2(aG[p]);
            float2 ov = unpack2(aO[p]);
            float ce = sigf(fv.x) * cst[2*p]     + sigf(iv.x) * tanhfast(gv.x);
            float co = sigf(fv.y) * cst[2*p + 1] + sigf(iv.y) * tanhfast(gv.y);
            cst[2*p] = ce; cst[2*p + 1] = co;
            float he = sigf(ov.x) * tanhfast(ce);
            float ho = sigf(ov.y) * tanhfast(co);
            hmax[2*p]     = fmaxf(hmax[2*p], he);
            hmax[2*p + 1] = fmaxf(hmax[2*p + 1], ho);
            float ae = __ldg(&g_scores[mrow[2*p]     * T_STEPS + t]);
            float ao = __ldg(&g_scores[mrow[2*p + 1] * T_STEPS + t]);
            hatt[2*p]     = fmaf(he, ae, hatt[2*p]);
            hatt[2*p + 1] = fmaf(ho, ao, hatt[2*p + 1]);
            hs[buf ^ 1][u][p] = make_float2(he, ho);
            if (t == 0) {
                g_pre[(r0 + 2*p)     * 1024 + dir * HID + u] = he;
                g_pre[(r0 + 2*p + 1) * 1024 + dir * HID + u] = ho;
            }
            if (t == T_STEPS - 1) {
                g_pre[(r0 + 2*p)     * 1024 + 256 + dir * HID + u] = he;
                g_pre[(r0 + 2*p + 1) * 1024 + 256 + dir * HID + u] = ho;
            }
        }

        // hoist next step's x-gate loads above the barrier (latency hiding)
        if (s + 1 < T_STEPS) {
            int tn = dir ? (T_STEPS - 2 - s) : (s + 1);
            long base = ((long)(dir * T_STEPS + tn) * (Mrows >> 1) + (r0 >> 1)) * HID + u;
#pragma unroll
            for (int p = 0; p < NP; p++) {
                ulonglong2 xA = g_XA[base + (long)p * HID];
                ulonglong2 xB = g_XB[base + (long)p * HID];
                aI[p] = xA.x; aF[p] = xA.y; aG[p] = xB.x; aO[p] = xB.y;
            }
        }
        __syncthreads();  // single barrier per step (double-buffered h)
        buf ^= 1;
    }

#pragma unroll
    for (int r = 0; r < ROWS; r++) {
        g_pre[(r0 + r) * 1024 + 512 + dir * HID + u] = hmax[r];
        g_pre[(r0 + r) * 1024 + 768 + dir * HID + u] = hatt[r];
    }
}

// ---------------------------------------------------------------------------
// Kernel 5: out = relu(pre(M,1024) @ enc_W(1024,128) + enc_b)
// ---------------------------------------------------------------------------
__global__ void __launch_bounds__(128)
out_kernel(const float* __restrict__ encW, const float* __restrict__ encB,
           float* __restrict__ out) {
    const int R2 = 8;
    int r0 = blockIdx.x * R2;
    int c  = threadIdx.x;
    __shared__ float2 ps[R2 / 2][64];

    float bc = encB[c];
    ull acc[R2 / 2];
#pragma unroll
    for (int p = 0; p < R2 / 2; p++) acc[p] = pack2(bc, bc);

    for (int kt = 0; kt < 1024; kt += 64) {
        __syncthreads();
#pragma unroll
        for (int i = 0; i < 4; i++) {
            int idx = c + i * 128;           // 0..511 over (r, kk)
            int r = idx >> 6, kk = idx & 63;
            ((float*)&ps[r >> 1][kk])[r & 1] = g_pre[(r0 + r) * 1024 + kt + kk];
        }
        __syncthreads();
#pragma unroll 4
        for (int kk = 0; kk < 64; kk++) {
            float w = encW[(kt + kk) * 128 + c];
            ull w2 = pack2(w, w);
#pragma unroll
            for (int p = 0; p < R2 / 2; p++) {
                ull pv = *(const ull*)&ps[p][kk];
                fma2(acc[p], pv, w2);
            }
        }
    }
#pragma unroll
    for (int p = 0; p < R2 / 2; p++) {
        float2 v = unpack2(acc[p]);
        out[(r0 + 2 * p)     * 128 + c] = fmaxf(v.x, 0.0f);
        out[(r0 + 2 * p + 1) * 128 + c] = fmaxf(v.y, 0.0f);
    }
}

// ---------------------------------------------------------------------------
// Launch
// ---------------------------------------------------------------------------
extern "C" void kernel_launch(void* const* d_in, const int* in_sizes, int n_in,
                              void* d_out, int out_size) {
    const float* lf    = (const float*)d_in[0];
    const float* obs   = (const float*)d_in[1];
    const float* embW  = (const float*)d_in[2];
    const float* embB  = (const float*)d_in[3];
    const float* attW  = (const float*)d_in[4];
    const float* attB  = (const float*)d_in[5];
    const float* Wih_f = (const float*)d_in[6];
    const float* Whh_f = (const float*)d_in[7];
    const float* b_f   = (const float*)d_in[8];
    const float* Wih_b = (const float*)d_in[9];
    const float* Whh_b = (const float*)d_in[10];
    const float* b_b   = (const float*)d_in[11];
    const float* h0    = (const float*)d_in[12];
    const float* c0    = (const float*)d_in[13];
    const float* encW  = (const float*)d_in[14];
    const float* encB  = (const float*)d_in[15];
    const int*   mask  = (const int*)d_in[16];

    int M    = in_sizes[16];       // 4096
    int Nobs = in_sizes[1] / 128;  // 256

    pack_kernel<<<(2 * 192 * GDIM + 255) / 256, 256>>>(Wih_f, Whh_f, Wih_b, Whh_b);
    attn_kernel<<<Nobs, 128>>>(obs, attW, attB);
    xgate_kernel<<<2 * (M / ROWS), 128>>>(lf, embW, embB, b_f, b_b, M);
    lstm_kernel<<<2 * (M / ROWS), 128>>>(h0, c0, mask, M);
    out_kernel<<<M / 8, 128>>>(encW, encB, (float*)d_out);
}

// round 14
// speedup vs baseline: 2.6492x; 2.3363x over previous
#include <cuda_runtime.h>
#include <cuda_bf16.h>
#include <math.h>

// ---------------------------------------------------------------------------
// AttentionalLaneLSTM: M=4096, N=256, EMB=64, H=128, ENC=128, T=100.
// Recurrence on tensor cores: G[64x512] = bias + [h|e][64x192] @ [Whh;Wih]
// via mma.sync.m16n8k16 bf16, 3-term hi/lo split for ~fp32 accuracy.
// ---------------------------------------------------------------------------
#define M_MAX   4096
#define T_STEPS 100
#define EMBD    64
#define HID     128
#define NOBS    256
#define MR      64            // rows per lstm CTA
#define KT      12            // 192/16 k-tiles (k<128 -> Whh, k>=128 -> Wih)
#define XS      200           // X smem row stride (bf16 elems), 400B

typedef unsigned int uint;

// Scratch (device globals — no dynamic allocation allowed)
__device__ float g_scores[NOBS * T_STEPS];
// fragment-ready B: [dir][ntile 64][ktile 12][lane 32] -> uint2
//  n = nt*8 + lane/4 ; k0 = kt*16 + 2*(lane&3); .x={k0,k0+1} .y={k0+8,k0+9}
__device__ uint2 g_Bhi[2 * 64 * KT * 32];
__device__ uint2 g_Blo[2 * 64 * KT * 32];
// embeddings e[t][row][64] bf16 hi/lo (dir-independent)
__device__ __nv_bfloat16 g_ehi[(long)T_STEPS * M_MAX * EMBD];
__device__ __nv_bfloat16 g_elo[(long)T_STEPS * M_MAX * EMBD];
__device__ float g_pre[M_MAX * 1024];

typedef unsigned long long ull;
__device__ __forceinline__ ull pack2(float a, float b) {
    ull r; asm("mov.b64 %0, {%1,%2};" : "=l"(r) : "f"(a), "f"(b)); return r;
}
__device__ __forceinline__ float2 unpack2(ull v) {
    float2 r; asm("mov.b64 {%0,%1}, %2;" : "=f"(r.x), "=f"(r.y) : "l"(v)); return r;
}
__device__ __forceinline__ void fma2(ull& acc, ull a, ull b) {
    asm("fma.rn.f32x2 %0, %1, %2, %0;" : "+l"(acc) : "l"(a), "l"(b));
}
__device__ __forceinline__ uint s2u(const void* p) {
    return (uint)__cvta_generic_to_shared(p);
}
__device__ __forceinline__ uint pkbf(float lo, float hi) {
    __nv_bfloat162 v = __floats2bfloat162_rn(lo, hi);
    return *(uint*)&v;
}
__device__ __forceinline__ float sigf(float x) {
    return __fdividef(1.0f, 1.0f + __expf(-x));
}
__device__ __forceinline__ float tanhfast(float x) {
    return __fdividef(2.0f, 1.0f + __expf(-2.0f * x)) - 1.0f;
}

#define LDM4(R, addr) \
    asm volatile("ldmatrix.sync.aligned.m8n8.x4.shared.b16 {%0,%1,%2,%3}, [%4];" \
                 : "=r"((R)[0]), "=r"((R)[1]), "=r"((R)[2]), "=r"((R)[3]) : "r"(addr))
#define MMAB(D, A, b) \
    asm volatile("mma.sync.aligned.m16n8k16.row.col.f32.bf16.bf16.f32 " \
                 "{%0,%1,%2,%3}, {%4,%5,%6,%7}, {%8,%9}, {%0,%1,%2,%3};" \
                 : "+f"((D)[0]), "+f"((D)[1]), "+f"((D)[2]), "+f"((D)[3]) \
                 : "r"((A)[0]), "r"((A)[1]), "r"((A)[2]), "r"((A)[3]), \
                   "r"((b).x), "r"((b).y))

// ---------------------------------------------------------------------------
// Kernel 1: build fragment-ready B tables (bf16 hi/lo split)
// ---------------------------------------------------------------------------
__global__ void pack_kernel(const float* __restrict__ Wih_f,
                            const float* __restrict__ Whh_f,
                            const float* __restrict__ Wih_b,
                            const float* __restrict__ Whh_b) {
    int idx = blockIdx.x * blockDim.x + threadIdx.x;
    if (idx >= 2 * 64 * KT * 32) return;
    int lane = idx & 31;
    int kt   = (idx >> 5) % KT;
    int nt   = (idx >> 5) / KT % 64;
    int d    = idx / (64 * KT * 32);
    int n  = nt * 8 + (lane >> 2);
    int k0 = kt * 16 + 2 * (lane & 3);
    const float* Whh = d ? Whh_b : Whh_f;
    const float* Wih = d ? Wih_b : Wih_f;
    float wv[4]; float hi[4], lo[4];
#pragma unroll
    for (int i = 0; i < 4; i++) {
        int k = k0 + (i >> 1) * 8 + (i & 1);
        wv[i] = (k < HID) ? Whh[k * 512 + n] : Wih[(k - HID) * 512 + n];
        hi[i] = __bfloat162float(__float2bfloat16(wv[i]));
        lo[i] = wv[i] - hi[i];
    }
    uint2 H, L;
    H.x = pkbf(hi[0], hi[1]); H.y = pkbf(hi[2], hi[3]);
    L.x = pkbf(lo[0], lo[1]); L.y = pkbf(lo[2], lo[3]);
    g_Bhi[idx] = H;
    g_Blo[idx] = L;
}

// ---------------------------------------------------------------------------
// Kernel 2: attention scores = softmax(relu(obs @ attn_W + attn_b), axis=1)
// ---------------------------------------------------------------------------
__global__ void attn_kernel(const float* __restrict__ obs,
                            const float* __restrict__ W,
                            const float* __restrict__ b) {
    int n = blockIdx.x, tid = threadIdx.x;
    __shared__ float obs_s[128];
    __shared__ float red[128];
    obs_s[tid] = obs[n * 128 + tid];
    __syncthreads();
    float a = -1e30f;
    if (tid < T_STEPS) {
        a = b[tid];
#pragma unroll 8
        for (int k = 0; k < 128; k++) a = fmaf(obs_s[k], W[k * T_STEPS + tid], a);
        a = fmaxf(a, 0.0f);
    }
    red[tid] = a;
    __syncthreads();
    for (int s = 64; s > 0; s >>= 1) {
        if (tid < s) red[tid] = fmaxf(red[tid], red[tid + s]);
        __syncthreads();
    }
    float m = red[0];
    __syncthreads();
    float e = 0.0f;
    if (tid < T_STEPS) e = expf(a - m);
    red[tid] = e;
    __syncthreads();
    for (int s = 64; s > 0; s >>= 1) {
        if (tid < s) red[tid] += red[tid + s];
        __syncthreads();
    }
    if (tid < T_STEPS) g_scores[n * T_STEPS + tid] = e / red[0];
}

// ---------------------------------------------------------------------------
// Kernel 3: embeddings e[t][row][64] = relu(feat4 @ embW + embB), bf16 hi/lo
// ---------------------------------------------------------------------------
__global__ void embed_kernel(const float* __restrict__ lf,
                             const float* __restrict__ embW,
                             const float* __restrict__ embB, int Mrows) {
    long idx = (long)blockIdx.x * blockDim.x + threadIdx.x;
    long total = (long)T_STEPS * Mrows * EMBD;
    if (idx >= total) return;
    int j   = (int)(idx & 63);
    long q  = idx >> 6;
    int row = (int)(q % Mrows);
    int t   = (int)(q / Mrows);
    const float* fb = lf + (long)row * 600 + 200 + t * 4;
    float v = embB[j];
    v = fmaf(fb[0], embW[j],        v);
    v = fmaf(fb[1], embW[64  + j],  v);
    v = fmaf(fb[2], embW[128 + j],  v);
    v = fmaf(fb[3], embW[192 + j],  v);
    v = fmaxf(v, 0.0f);
    float hi = __bfloat162float(__float2bfloat16(v));
    g_ehi[idx] = __float2bfloat16(v);
    g_elo[idx] = __float2bfloat16(v - hi);
}

// ---------------------------------------------------------------------------
// Kernel 4: tensor-core bidirectional LSTM.
// 512 threads (16 warps), 64 rows, 1 dir per CTA; grid 128 = 1 wave.
// Warp w: m-tile (w&3) = 16 rows; unit quarter q=(w>>2) = 32 units ->
// 16 n-tiles (4 unit-tiles x 4 gates, nt = g*16 + q*4 + ut). Thread owns
// rows {rA,rA+8} x units {uA,uA+1} per tile -> cell update thread-local.
// X smem = [h(0..127) | e(128..191)] bf16, hi & lo buffers, stride 200.
// ---------------------------------------------------------------------------
extern __shared__ char dynsmem[];

__global__ void __launch_bounds__(512, 1)
lstm_kernel(const float* __restrict__ h0, const float* __restrict__ c0,
            const float* __restrict__ b_f, const float* __restrict__ b_b,
            const int*   __restrict__ mask, int Mrows) {
    int nblk = Mrows / MR;                 // 64
    int dir  = blockIdx.x / nblk;
    int mblk = blockIdx.x % nblk;
    int r0   = mblk * MR;
    int tid  = threadIdx.x;
    int w = tid >> 5, lane = tid & 31;
    int mt = w & 3, q = w >> 2;

    __nv_bfloat16* Xhi = (__nv_bfloat16*)(dynsmem);            // 25600 B
    __nv_bfloat16* Xlo = (__nv_bfloat16*)(dynsmem + 25600);    // 25600 B
    float* smax = (float*)(dynsmem + 51200);                   // 64*133*4
    float* satt = (float*)(dynsmem + 85248);
    float* sb   = (float*)(dynsmem + 119296);                  // 512 bias
    int*   smrow= (int*)(dynsmem + 121344);                    // 64

    const float* bias = dir ? b_b : b_f;
    if (tid < 512) sb[tid] = bias[tid];
    if (tid < MR) smrow[tid] = mask[r0 + tid];
    // init h columns of X from h0, init smax/satt
    for (int i = tid; i < MR * HID; i += 512) {
        int row = i >> 7, u = i & 127;
        float h = h0[dir * HID + u];
        float hh = __bfloat162float(__float2bfloat16(h));
        Xhi[row * XS + u] = __float2bfloat16(h);
        Xlo[row * XS + u] = __float2bfloat16(h - hh);
        smax[row * 133 + u] = -1e30f;
        satt[row * 133 + u] = 0.0f;
    }
    // stage e for first step
    {
        int t0 = dir ? (T_STEPS - 1) : 0;
        const uint4* sh = (const uint4*)(g_ehi + ((long)t0 * Mrows + r0) * EMBD);
        const uint4* sl = (const uint4*)(g_elo + ((long)t0 * Mrows + r0) * EMBD);
        int row = tid >> 3, c8 = tid & 7;
        *(uint4*)&Xhi[row * XS + HID + c8 * 8] = sh[tid];
        *(uint4*)&Xlo[row * XS + HID + c8 * 8] = sl[tid];
    }
    __syncthreads();

    // per-thread cell state cst[ut][j], j: 0=(rA,uA) 1=(rA,uA+1) 2=(rB,uA) 3=(rB,uA+1)
    int rA = mt * 16 + (lane >> 2);
    float cst[4][4];
#pragma unroll
    for (int ut = 0; ut < 4; ut++) {
        int uA = q * 32 + ut * 8 + 2 * (lane & 3);
        float cA = c0[dir * HID + uA], cB = c0[dir * HID + uA + 1];
        cst[ut][0] = cA; cst[ut][1] = cB; cst[ut][2] = cA; cst[ut][3] = cB;
    }

    // ldmatrix source: matrices TL,BL,TR,BR of the 16x16 A tile
    int arow = mt * 16 + (lane & 7) + ((lane >> 3) & 1) * 8;
    int acolb = ((lane >> 4) & 1) * 8;
    uint a_hi = s2u(Xhi + arow * XS + acolb);
    uint a_lo = s2u(Xlo + arow * XS + acolb);

    const uint2* Bhi0 = g_Bhi + ((long)(dir * 64 + q * 4) * KT) * 32 + lane;
    const uint2* Blo0 = g_Blo + ((long)(dir * 64 + q * 4) * KT) * 32 + lane;

    for (int s = 0; s < T_STEPS; s++) {
        int t = dir ? (T_STEPS - 1 - s) : s;

        float acc[4][4][4];
#pragma unroll
        for (int ut = 0; ut < 4; ut++)
#pragma unroll
            for (int g = 0; g < 4; g++)
#pragma unroll
                for (int j = 0; j < 4; j++) acc[ut][g][j] = 0.0f;

        for (int kt = 0; kt < KT; kt++) {
            uint Ah[4], Al[4];
            LDM4(Ah, a_hi + kt * 32);
            LDM4(Al, a_lo + kt * 32);
#pragma unroll
            for (int g = 0; g < 4; g++)
#pragma unroll
                for (int ut = 0; ut < 4; ut++) {
                    long off = (long)(g * 16 + ut) * KT * 32 + kt * 32;
                    uint2 bh = Bhi0[off];
                    uint2 bl = Blo0[off];
                    MMAB(acc[ut][g], Ah, bh);
                    MMAB(acc[ut][g], Ah, bl);
                    MMAB(acc[ut][g], Al, bh);
                }
        }
        __syncthreads();   // all warps done reading X

        // epilogue: thread-local cell update + reductions + h republish
#pragma unroll
        for (int ut = 0; ut < 4; ut++) {
            int uA = q * 32 + ut * 8 + 2 * (lane & 3);
#pragma unroll
            for (int j = 0; j < 4; j++) {
                int u = uA + (j & 1);
                int row = rA + (j >> 1) * 8;
                float gi = acc[ut][0][j] + sb[u];
                float gf = acc[ut][1][j] + sb[128 + u];
                float gg = acc[ut][2][j] + sb[256 + u];
                float go = acc[ut][3][j] + sb[384 + u];
                float c = sigf(gf) * cst[ut][j] + sigf(gi) * tanhfast(gg);
                cst[ut][j] = c;
                float h = sigf(go) * tanhfast(c);
                float hh = __bfloat162float(__float2bfloat16(h));
                Xhi[row * XS + u] = __float2bfloat16(h);
                Xlo[row * XS + u] = __float2bfloat16(h - hh);
                float av = __ldg(&g_scores[smrow[row] * T_STEPS + t]);
                smax[row * 133 + u] = fmaxf(smax[row * 133 + u], h);
                satt[row * 133 + u] = fmaf(h, av, satt[row * 133 + u]);
                if (t == 0)
                    g_pre[(r0 + row) * 1024 + dir * HID + u] = h;
                if (t == T_STEPS - 1)
                    g_pre[(r0 + row) * 1024 + 256 + dir * HID + u] = h;
            }
        }
        // stage e for next step
        if (s + 1 < T_STEPS) {
            int tn = dir ? (T_STEPS - 2 - s) : (s + 1);
            const uint4* sh = (const uint4*)(g_ehi + ((long)tn * Mrows + r0) * EMBD);
            const uint4* sl = (const uint4*)(g_elo + ((long)tn * Mrows + r0) * EMBD);
            int row = tid >> 3, c8 = tid & 7;
            *(uint4*)&Xhi[row * XS + HID + c8 * 8] = sh[tid];
            *(uint4*)&Xlo[row * XS + HID + c8 * 8] = sl[tid];
        }
        __syncthreads();   // X updated before next mma
    }

    // write max / attn sections
    for (int i = tid; i < MR * HID; i += 512) {
        int row = i >> 7, u = i & 127;
        g_pre[(r0 + row) * 1024 + 512 + dir * HID + u] = smax[row * 133 + u];
        g_pre[(r0 + row) * 1024 + 768 + dir * HID + u] = satt[row * 133 + u];
    }
}

// ---------------------------------------------------------------------------
// Kernel 5: out = relu(pre(M,1024) @ enc_W(1024,128) + enc_b)
// ---------------------------------------------------------------------------
__global__ void __launch_bounds__(128)
out_kernel(const float* __restrict__ encW, const float* __restrict__ encB,
           float* __restrict__ out) {
    const int R2 = 8;
    int r0 = blockIdx.x * R2;
    int c  = threadIdx.x;
    __shared__ float2 ps[R2 / 2][64];

    float bc = encB[c];
    ull acc[R2 / 2];
#pragma unroll
    for (int p = 0; p < R2 / 2; p++) acc[p] = pack2(bc, bc);

    for (int kt = 0; kt < 1024; kt += 64) {
        __syncthreads();
#pragma unroll
        for (int i = 0; i < 4; i++) {
            int idx = c + i * 128;
            int r = idx >> 6, kk = idx & 63;
            ((float*)&ps[r >> 1][kk])[r & 1] = g_pre[(r0 + r) * 1024 + kt + kk];
        }
        __syncthreads();
#pragma unroll 4
        for (int kk = 0; kk < 64; kk++) {
            float w = encW[(kt + kk) * 128 + c];
            ull w2 = pack2(w, w);
#pragma unroll
            for (int p = 0; p < R2 / 2; p++) {
                ull pv = *(const ull*)&ps[p][kk];
                fma2(acc[p], pv, w2);
            }
        }
    }
#pragma unroll
    for (int p = 0; p < R2 / 2; p++) {
        float2 v = unpack2(acc[p]);
        out[(r0 + 2 * p)     * 128 + c] = fmaxf(v.x, 0.0f);
        out[(r0 + 2 * p + 1) * 128 + c] = fmaxf(v.y, 0.0f);
    }
}

// ---------------------------------------------------------------------------
// Launch
// ---------------------------------------------------------------------------
#define LSTM_SMEM 121600

extern "C" void kernel_launch(void* const* d_in, const int* in_sizes, int n_in,
                              void* d_out, int out_size) {
    const float* lf    = (const float*)d_in[0];
    const float* obs   = (const float*)d_in[1];
    const float* embW  = (const float*)d_in[2];
    const float* embB  = (const float*)d_in[3];
    const float* attW  = (const float*)d_in[4];
    const float* attB  = (const float*)d_in[5];
    const float* Wih_f = (const float*)d_in[6];
    const float* Whh_f = (const float*)d_in[7];
    const float* b_f   = (const float*)d_in[8];
    const float* Wih_b = (const float*)d_in[9];
    const float* Whh_b = (const float*)d_in[10];
    const float* b_b   = (const float*)d_in[11];
    const float* h0    = (const float*)d_in[12];
    const float* c0    = (const float*)d_in[13];
    const float* encW  = (const float*)d_in[14];
    const float* encB  = (const float*)d_in[15];
    const int*   mask  = (const int*)d_in[16];

    int M    = in_sizes[16];       // 4096
    int Nobs = in_sizes[1] / 128;  // 256

    static int smem_set = 0;
    if (!smem_set) {
        cudaFuncSetAttribute(lstm_kernel,
                             cudaFuncAttributeMaxDynamicSharedMemorySize, LSTM_SMEM);
        smem_set = 1;
    }

    pack_kernel<<<(2 * 64 * KT * 32 + 255) / 256, 256>>>(Wih_f, Whh_f, Wih_b, Whh_b);
    attn_kernel<<<Nobs, 128>>>(obs, attW, attB);
    long etotal = (long)T_STEPS * M * EMBD;
    embed_kernel<<<(int)((etotal + 255) / 256), 256>>>(lf, embW, embB, M);
    lstm_kernel<<<2 * (M / MR), 512, LSTM_SMEM>>>(h0, c0, b_f, b_b, mask, M);
    out_kernel<<<M / 8, 128>>>(encW, encB, (float*)d_out);
}

// round 15
// speedup vs baseline: 3.1257x; 1.1799x over previous
#include <cuda_runtime.h>
#include <cuda_bf16.h>
#include <math.h>

// ---------------------------------------------------------------------------
// AttentionalLaneLSTM: M=4096, N=256, EMB=64, H=128, ENC=128, T=100.
// Tensor-core recurrence: G[64x512] = bias + [h|e][64x192] @ [Whh;Wih]
// via mma.sync.m16n8k16 bf16, 3-term hi/lo split (~fp32 accuracy).
// R15: double-buffered X (1 barrier/step), term-major mma ordering
// (dep distance 4), fused float2 reductions, packed h-stores.
// ---------------------------------------------------------------------------
#define M_MAX   4096
#define T_STEPS 100
#define EMBD    64
#define HID     128
#define NOBS    256
#define MR      64            // rows per lstm CTA
#define KT      12            // 192/16 k-tiles (k<128 -> Whh, k>=128 -> Wih)
#define XS      200           // X smem row stride (bf16 elems)
#define SRS     132           // sred row stride (float2 elems)

typedef unsigned int uint;
typedef unsigned long long ull;

// Scratch (device globals — no dynamic allocation allowed)
__device__ float g_scores[NOBS * T_STEPS];
// fragment-ready B: [dir][ntile 64][ktile 12][lane 32] -> uint2
//  n = nt*8 + lane/4 ; k0 = kt*16 + 2*(lane&3); .x={k0,k0+1} .y={k0+8,k0+9}
__device__ uint2 g_Bhi[2 * 64 * KT * 32];
__device__ uint2 g_Blo[2 * 64 * KT * 32];
// embeddings e[t][row][64] bf16 hi/lo (dir-independent)
__device__ __nv_bfloat16 g_ehi[(long)T_STEPS * M_MAX * EMBD];
__device__ __nv_bfloat16 g_elo[(long)T_STEPS * M_MAX * EMBD];
__device__ float g_pre[M_MAX * 1024];

__device__ __forceinline__ ull pack2(float a, float b) {
    ull r; asm("mov.b64 %0, {%1,%2};" : "=l"(r) : "f"(a), "f"(b)); return r;
}
__device__ __forceinline__ float2 unpack2(ull v) {
    float2 r; asm("mov.b64 {%0,%1}, %2;" : "=f"(r.x), "=f"(r.y) : "l"(v)); return r;
}
__device__ __forceinline__ void fma2(ull& acc, ull a, ull b) {
    asm("fma.rn.f32x2 %0, %1, %2, %0;" : "+l"(acc) : "l"(a), "l"(b));
}
__device__ __forceinline__ uint s2u(const void* p) {
    return (uint)__cvta_generic_to_shared(p);
}
__device__ __forceinline__ uint pkbf(float lo, float hi) {
    __nv_bfloat162 v = __floats2bfloat162_rn(lo, hi);
    return *(uint*)&v;
}
__device__ __forceinline__ float sigf(float x) {
    return __fdividef(1.0f, 1.0f + __expf(-x));
}
__device__ __forceinline__ float tanhfast(float x) {
    return __fdividef(2.0f, 1.0f + __expf(-2.0f * x)) - 1.0f;
}

#define LDM4(R, addr) \
    asm volatile("ldmatrix.sync.aligned.m8n8.x4.shared.b16 {%0,%1,%2,%3}, [%4];" \
                 : "=r"((R)[0]), "=r"((R)[1]), "=r"((R)[2]), "=r"((R)[3]) : "r"(addr))
#define MMAB(D, A, b) \
    asm volatile("mma.sync.aligned.m16n8k16.row.col.f32.bf16.bf16.f32 " \
                 "{%0,%1,%2,%3}, {%4,%5,%6,%7}, {%8,%9}, {%0,%1,%2,%3};" \
                 : "+f"((D)[0]), "+f"((D)[1]), "+f"((D)[2]), "+f"((D)[3]) \
                 : "r"((A)[0]), "r"((A)[1]), "r"((A)[2]), "r"((A)[3]), \
                   "r"((b).x), "r"((b).y))

// ---------------------------------------------------------------------------
// Kernel 1: build fragment-ready B tables (bf16 hi/lo split)
// ---------------------------------------------------------------------------
__global__ void pack_kernel(const float* __restrict__ Wih_f,
                            const float* __restrict__ Whh_f,
                            const float* __restrict__ Wih_b,
                            const float* __restrict__ Whh_b) {
    int idx = blockIdx.x * blockDim.x + threadIdx.x;
    if (idx >= 2 * 64 * KT * 32) return;
    int lane = idx & 31;
    int kt   = (idx >> 5) % KT;
    int nt   = (idx >> 5) / KT % 64;
    int d    = idx / (64 * KT * 32);
    int n  = nt * 8 + (lane >> 2);
    int k0 = kt * 16 + 2 * (lane & 3);
    const float* Whh = d ? Whh_b : Whh_f;
    const float* Wih = d ? Wih_b : Wih_f;
    float wv[4]; float hi[4], lo[4];
#pragma unroll
    for (int i = 0; i < 4; i++) {
        int k = k0 + (i >> 1) * 8 + (i & 1);
        wv[i] = (k < HID) ? Whh[k * 512 + n] : Wih[(k - HID) * 512 + n];
        hi[i] = __bfloat162float(__float2bfloat16(wv[i]));
        lo[i] = wv[i] - hi[i];
    }
    uint2 H, L;
    H.x = pkbf(hi[0], hi[1]); H.y = pkbf(hi[2], hi[3]);
    L.x = pkbf(lo[0], lo[1]); L.y = pkbf(lo[2], lo[3]);
    g_Bhi[idx] = H;
    g_Blo[idx] = L;
}

// ---------------------------------------------------------------------------
// Kernel 2: attention scores = softmax(relu(obs @ attn_W + attn_b), axis=1)
// ---------------------------------------------------------------------------
__global__ void attn_kernel(const float* __restrict__ obs,
                            const float* __restrict__ W,
                            const float* __restrict__ b) {
    int n = blockIdx.x, tid = threadIdx.x;
    __shared__ float obs_s[128];
    __shared__ float red[128];
    obs_s[tid] = obs[n * 128 + tid];
    __syncthreads();
    float a = -1e30f;
    if (tid < T_STEPS) {
        a = b[tid];
#pragma unroll 8
        for (int k = 0; k < 128; k++) a = fmaf(obs_s[k], W[k * T_STEPS + tid], a);
        a = fmaxf(a, 0.0f);
    }
    red[tid] = a;
    __syncthreads();
    for (int s = 64; s > 0; s >>= 1) {
        if (tid < s) red[tid] = fmaxf(red[tid], red[tid + s]);
        __syncthreads();
    }
    float m = red[0];
    __syncthreads();
    float e = 0.0f;
    if (tid < T_STEPS) e = expf(a - m);
    red[tid] = e;
    __syncthreads();
    for (int s = 64; s > 0; s >>= 1) {
        if (tid < s) red[tid] += red[tid + s];
        __syncthreads();
    }
    if (tid < T_STEPS) g_scores[n * T_STEPS + tid] = e / red[0];
}

// ---------------------------------------------------------------------------
// Kernel 3: embeddings e[t][row][64] = relu(feat4 @ embW + embB), bf16 hi/lo
// ---------------------------------------------------------------------------
__global__ void embed_kernel(const float* __restrict__ lf,
                             const float* __restrict__ embW,
                             const float* __restrict__ embB, int Mrows) {
    long idx = (long)blockIdx.x * blockDim.x + threadIdx.x;
    long total = (long)T_STEPS * Mrows * EMBD;
    if (idx >= total) return;
    int j   = (int)(idx & 63);
    long q  = idx >> 6;
    int row = (int)(q % Mrows);
    int t   = (int)(q / Mrows);
    const float* fb = lf + (long)row * 600 + 200 + t * 4;
    float v = embB[j];
    v = fmaf(fb[0], embW[j],        v);
    v = fmaf(fb[1], embW[64  + j],  v);
    v = fmaf(fb[2], embW[128 + j],  v);
    v = fmaf(fb[3], embW[192 + j],  v);
    v = fmaxf(v, 0.0f);
    float hi = __bfloat162float(__float2bfloat16(v));
    g_ehi[idx] = __float2bfloat16(v);
    g_elo[idx] = __float2bfloat16(v - hi);
}

// ---------------------------------------------------------------------------
// Kernel 4: tensor-core bidirectional LSTM, double-buffered X.
// 512 threads (16 warps), 64 rows, 1 dir per CTA; grid 128.
// Warp w: m-tile (w&3), unit quarter q=(w>>2). Per step:
//   mma (reads X[cur]) -> epilogue writes h into X[nxt] (packed uint stores)
//   + e-stage writes e cols of X[nxt] -> ONE barrier -> swap.
// MMA inner loop: per (kt,g) load 4 bh + 4 bl, issue hh x4, hl x4, lh x4
// (same-acc dependency distance = 4 mmas).
// ---------------------------------------------------------------------------
extern __shared__ char dynsmem[];

#define OFF_XHI0 0
#define OFF_XHI1 25600
#define OFF_XLO0 51200
#define OFF_XLO1 76800
#define OFF_SRED 102400                     // float2[64][SRS] = 67584 B
#define OFF_SB   (OFF_SRED + 64 * SRS * 8)  // 169984
#define OFF_MROW (OFF_SB + 2048)            // 172032
#define LSTM_SMEM (OFF_MROW + 256)          // 172288

__global__ void __launch_bounds__(512, 1)
lstm_kernel(const float* __restrict__ h0, const float* __restrict__ c0,
            const float* __restrict__ b_f, const float* __restrict__ b_b,
            const int*   __restrict__ mask, int Mrows) {
    int nblk = Mrows / MR;                 // 64
    int dir  = blockIdx.x / nblk;
    int mblk = blockIdx.x % nblk;
    int r0   = mblk * MR;
    int tid  = threadIdx.x;
    int w = tid >> 5, lane = tid & 31;
    int mt = w & 3, q = w >> 2;
    int tq = lane & 3;

    __nv_bfloat16* Xhi[2] = { (__nv_bfloat16*)(dynsmem + OFF_XHI0),
                              (__nv_bfloat16*)(dynsmem + OFF_XHI1) };
    __nv_bfloat16* Xlo[2] = { (__nv_bfloat16*)(dynsmem + OFF_XLO0),
                              (__nv_bfloat16*)(dynsmem + OFF_XLO1) };
    float2* sred = (float2*)(dynsmem + OFF_SRED);  // (hmax, hatt) per (row,u)
    float*  sb   = (float*)(dynsmem + OFF_SB);
    int*    smrow= (int*)(dynsmem + OFF_MROW);

    const float* bias = dir ? b_b : b_f;
    sb[tid] = bias[tid];
    if (tid < MR) smrow[tid] = mask[r0 + tid];
    // init h columns of X[0], init sred
    for (int i = tid; i < MR * HID; i += 512) {
        int row = i >> 7, u = i & 127;
        float h = h0[dir * HID + u];
        float hh = __bfloat162float(__float2bfloat16(h));
        Xhi[0][row * XS + u] = __float2bfloat16(h);
        Xlo[0][row * XS + u] = __float2bfloat16(h - hh);
        sred[row * SRS + u] = make_float2(-1e30f, 0.0f);
    }
    // stage e(t0) into X[0]
    {
        int t0 = dir ? (T_STEPS - 1) : 0;
        const uint4* sh = (const uint4*)(g_ehi + ((long)t0 * Mrows + r0) * EMBD);
        const uint4* sl = (const uint4*)(g_elo + ((long)t0 * Mrows + r0) * EMBD);
        int row = tid >> 3, c8 = tid & 7;
        *(uint4*)&Xhi[0][row * XS + HID + c8 * 8] = sh[tid];
        *(uint4*)&Xlo[0][row * XS + HID + c8 * 8] = sl[tid];
    }
    __syncthreads();

    // per-thread cell state cst[ut][j], j: 0=(rA,uA) 1=(rA,uA+1) 2=(rB,uA) 3=(rB,uA+1)
    int rA = mt * 16 + (lane >> 2);
    int rB = rA + 8;
    float cst[4][4];
#pragma unroll
    for (int ut = 0; ut < 4; ut++) {
        int uA = q * 32 + ut * 8 + 2 * tq;
        float cA = c0[dir * HID + uA], cB = c0[dir * HID + uA + 1];
        cst[ut][0] = cA; cst[ut][1] = cB; cst[ut][2] = cA; cst[ut][3] = cB;
    }

    // ldmatrix sources for both buffers (TL,BL,TR,BR of the 16x16 A tile)
    int arow = mt * 16 + (lane & 7) + ((lane >> 3) & 1) * 8;
    int acolb = ((lane >> 4) & 1) * 8;
    uint aHi[2] = { s2u(Xhi[0] + arow * XS + acolb), s2u(Xhi[1] + arow * XS + acolb) };
    uint aLo[2] = { s2u(Xlo[0] + arow * XS + acolb), s2u(Xlo[1] + arow * XS + acolb) };

    const uint2* Bhi0 = g_Bhi + ((long)(dir * 64 + q * 4) * KT) * 32 + lane;
    const uint2* Blo0 = g_Blo + ((long)(dir * 64 + q * 4) * KT) * 32 + lane;

    int cur = 0;
    for (int s = 0; s < T_STEPS; s++) {
        int t = dir ? (T_STEPS - 1 - s) : s;
        int nxt = cur ^ 1;

        float acc[4][4][4];
#pragma unroll
        for (int ut = 0; ut < 4; ut++)
#pragma unroll
            for (int g = 0; g < 4; g++)
#pragma unroll
                for (int j = 0; j < 4; j++) acc[ut][g][j] = 0.0f;

        for (int kt = 0; kt < KT; kt++) {
            uint Ah[4], Al[4];
            LDM4(Ah, aHi[cur] + kt * 32);
            LDM4(Al, aLo[cur] + kt * 32);
#pragma unroll
            for (int g = 0; g < 4; g++) {
                uint2 bh[4], bl[4];
#pragma unroll
                for (int ut = 0; ut < 4; ut++) {
                    long off = ((long)(g * 16 + ut) * KT + kt) * 32;
                    bh[ut] = Bhi0[off];
                    bl[ut] = Blo0[off];
                }
                // term-major: same-acc dependency distance = 4 mmas
#pragma unroll
                for (int ut = 0; ut < 4; ut++) MMAB(acc[ut][g], Ah, bh[ut]);
#pragma unroll
                for (int ut = 0; ut < 4; ut++) MMAB(acc[ut][g], Ah, bl[ut]);
#pragma unroll
                for (int ut = 0; ut < 4; ut++) MMAB(acc[ut][g], Al, bh[ut]);
            }
        }

        // attention weights (2 per thread per step)
        float avA = __ldg(&g_scores[smrow[rA] * T_STEPS + t]);
        float avB = __ldg(&g_scores[smrow[rB] * T_STEPS + t]);

        // epilogue: thread-local cell update; h written PACKED into X[nxt]
#pragma unroll
        for (int ut = 0; ut < 4; ut++) {
            int uA = q * 32 + ut * 8 + 2 * tq;
            float hv[4];
#pragma unroll
            for (int j = 0; j < 4; j++) {
                int u = uA + (j & 1);
                float gi = acc[ut][0][j] + sb[u];
                float gf = acc[ut][1][j] + sb[128 + u];
                float gg = acc[ut][2][j] + sb[256 + u];
                float go = acc[ut][3][j] + sb[384 + u];
                float c = sigf(gf) * cst[ut][j] + sigf(gi) * tanhfast(gg);
                cst[ut][j] = c;
                hv[j] = sigf(go) * tanhfast(c);
            }
            // packed bf16x2 stores: (u, u+1) pair per row
            float h0A = __bfloat162float(__float2bfloat16(hv[0]));
            float h1A = __bfloat162float(__float2bfloat16(hv[1]));
            float h0B = __bfloat162float(__float2bfloat16(hv[2]));
            float h1B = __bfloat162float(__float2bfloat16(hv[3]));
            *(uint*)&Xhi[nxt][rA * XS + uA] = pkbf(hv[0], hv[1]);
            *(uint*)&Xlo[nxt][rA * XS + uA] = pkbf(hv[0] - h0A, hv[1] - h1A);
            *(uint*)&Xhi[nxt][rB * XS + uA] = pkbf(hv[2], hv[3]);
            *(uint*)&Xlo[nxt][rB * XS + uA] = pkbf(hv[2] - h0B, hv[3] - h1B);
            // fused (hmax, hatt) float2 updates
#pragma unroll
            for (int j = 0; j < 4; j++) {
                int u = uA + (j & 1);
                int row = (j >> 1) ? rB : rA;
                float av = (j >> 1) ? avB : avA;
                float2 v = sred[row * SRS + u];
                v.x = fmaxf(v.x, hv[j]);
                v.y = fmaf(hv[j], av, v.y);
                sred[row * SRS + u] = v;
            }
            if (t == 0) {
                g_pre[(r0 + rA) * 1024 + dir * HID + uA]     = hv[0];
                g_pre[(r0 + rA) * 1024 + dir * HID + uA + 1] = hv[1];
                g_pre[(r0 + rB) * 1024 + dir * HID + uA]     = hv[2];
                g_pre[(r0 + rB) * 1024 + dir * HID + uA + 1] = hv[3];
            }
            if (t == T_STEPS - 1) {
                g_pre[(r0 + rA) * 1024 + 256 + dir * HID + uA]     = hv[0];
                g_pre[(r0 + rA) * 1024 + 256 + dir * HID + uA + 1] = hv[1];
                g_pre[(r0 + rB) * 1024 + 256 + dir * HID + uA]     = hv[2];
                g_pre[(r0 + rB) * 1024 + 256 + dir * HID + uA + 1] = hv[3];
            }
        }

        // stage e for next step into X[nxt]
        if (s + 1 < T_STEPS) {
            int tn = dir ? (T_STEPS - 2 - s) : (s + 1);
            const uint4* sh = (const uint4*)(g_ehi + ((long)tn * Mrows + r0) * EMBD);
            const uint4* sl = (const uint4*)(g_elo + ((long)tn * Mrows + r0) * EMBD);
            int row = tid >> 3, c8 = tid & 7;
            *(uint4*)&Xhi[nxt][row * XS + HID + c8 * 8] = sh[tid];
            *(uint4*)&Xlo[nxt][row * XS + HID + c8 * 8] = sl[tid];
        }
        __syncthreads();   // single barrier per step
        cur = nxt;
    }

    // write max / attn sections
    for (int i = tid; i < MR * HID; i += 512) {
        int row = i >> 7, u = i & 127;
        float2 v = sred[row * SRS + u];
        g_pre[(r0 + row) * 1024 + 512 + dir * HID + u] = v.x;
        g_pre[(r0 + row) * 1024 + 768 + dir * HID + u] = v.y;
    }
}

// ---------------------------------------------------------------------------
// Kernel 5: out = relu(pre(M,1024) @ enc_W(1024,128) + enc_b)
// ---------------------------------------------------------------------------
__global__ void __launch_bounds__(128)
out_kernel(const float* __restrict__ encW, const float* __restrict__ encB,
           float* __restrict__ out) {
    const int R2 = 8;
    int r0 = blockIdx.x * R2;
    int c  = threadIdx.x;
    __shared__ float2 ps[R2 / 2][64];

    float bc = encB[c];
    ull acc[R2 / 2];
#pragma unroll
    for (int p = 0; p < R2 / 2; p++) acc[p] = pack2(bc, bc);

    for (int kt = 0; kt < 1024; kt += 64) {
        __syncthreads();
#pragma unroll
        for (int i = 0; i < 4; i++) {
            int idx = c + i * 128;
            int r = idx >> 6, kk = idx & 63;
            ((float*)&ps[r >> 1][kk])[r & 1] = g_pre[(r0 + r) * 1024 + kt + kk];
        }
        __syncthreads();
#pragma unroll 4
        for (int kk = 0; kk < 64; kk++) {
            float w = encW[(kt + kk) * 128 + c];
            ull w2 = pack2(w, w);
#pragma unroll
            for (int p = 0; p < R2 / 2; p++) {
                ull pv = *(const ull*)&ps[p][kk];
                fma2(acc[p], pv, w2);
            }
        }
    }
#pragma unroll
    for (int p = 0; p < R2 / 2; p++) {
        float2 v = unpack2(acc[p]);
        out[(r0 + 2 * p)     * 128 + c] = fmaxf(v.x, 0.0f);
        out[(r0 + 2 * p + 1) * 128 + c] = fmaxf(v.y, 0.0f);
    }
}

// ---------------------------------------------------------------------------
// Launch
// ---------------------------------------------------------------------------
extern "C" void kernel_launch(void* const* d_in, const int* in_sizes, int n_in,
                              void* d_out, int out_size) {
    const float* lf    = (const float*)d_in[0];
    const float* obs   = (const float*)d_in[1];
    const float* embW  = (const float*)d_in[2];
    const float* embB  = (const float*)d_in[3];
    const float* attW  = (const float*)d_in[4];
    const float* attB  = (const float*)d_in[5];
    const float* Wih_f = (const float*)d_in[6];
    const float* Whh_f = (const float*)d_in[7];
    const float* b_f   = (const float*)d_in[8];
    const float* Wih_b = (const float*)d_in[9];
    const float* Whh_b = (const float*)d_in[10];
    const float* b_b   = (const float*)d_in[11];
    const float* h0    = (const float*)d_in[12];
    const float* c0    = (const float*)d_in[13];
    const float* encW  = (const float*)d_in[14];
    const float* encB  = (const float*)d_in[15];
    const int*   mask  = (const int*)d_in[16];

    int M    = in_sizes[16];       // 4096
    int Nobs = in_sizes[1] / 128;  // 256

    static int smem_set = 0;
    if (!smem_set) {
        cudaFuncSetAttribute(lstm_kernel,
                             cudaFuncAttributeMaxDynamicSharedMemorySize, LSTM_SMEM);
        smem_set = 1;
    }

    pack_kernel<<<(2 * 64 * KT * 32 + 255) / 256, 256>>>(Wih_f, Whh_f, Wih_b, Whh_b);
    attn_kernel<<<Nobs, 128>>>(obs, attW, attB);
    long etotal = (long)T_STEPS * M * EMBD;
    embed_kernel<<<(int)((etotal + 255) / 256), 256>>>(lf, embW, embB, M);
    lstm_kernel<<<2 * (M / MR), 512, LSTM_SMEM>>>(h0, c0, b_f, b_b, mask, M);
    out_kernel<<<M / 8, 128>>>(encW, encB, (float*)d_out);
}